// round 11
// baseline (speedup 1.0000x reference)
#include <cuda_runtime.h>
#include <cstdint>

// F=32, B=8192, D=64
// inputs: [F, B, 1, D] fp32 ; output: [B, D*D] fp32
// out[b, i*64+j] = s[b,i] * s[b,j], s = sum_f inputs[f,b,0,:]
//
// FINAL — floor confirmed across 10 rounds (6 distinct datapaths, all within
// 35.3-35.6us wall). The kernel is compulsory-traffic bound: 134MB output
// write stream at the DRAM mixed-stream ceiling (~5.6TB/s wall-effective);
// the 64MB input is L2-resident across graph replays. Best measured variant
// (35.296us, reproduced): fractional evict_last store policy (f=0.7 -> ~94MB
// sticky < 126MB L2, stable) + default-policy coalesced float4 loads.

#define F_DIM 32
#define B_DIM 8192
#define D_DIM 64
#define FB_STRIDE ((size_t)B_DIM * D_DIM)   // elements per field slab

__device__ __forceinline__ uint64_t make_policy_f70() {
    uint64_t pol;
    asm("createpolicy.fractional.L2::evict_last.b64 %0, 0.7;" : "=l"(pol));
    return pol;
}

__device__ __forceinline__ void stg_v4_hint(float4* p, float4 v, uint64_t pol) {
    asm volatile(
        "st.global.L2::cache_hint.v4.f32 [%0], {%1, %2, %3, %4}, %5;"
        :: "l"(p), "f"(v.x), "f"(v.y), "f"(v.z), "f"(v.w), "l"(pol)
        : "memory");
}

__global__ __launch_bounds__(256, 8)
void opnn_kernel(const float* __restrict__ in, float* __restrict__ out) {
    const int b   = blockIdx.x;
    const int tid = threadIdx.x;      // 256 threads
    const int d   = tid & 63;         // 0..63
    const int g   = tid >> 6;         // 0..3 (field group of 8)

    __shared__ float partial[4][64];
    __shared__ float s[64];

    const uint64_t pol = make_policy_f70();

    // Field-sum: each thread sums 8 fields for one d. Per-field access is a
    // contiguous 256B line across d (coalesced); 8 independent loads -> MLP
    // for latency hiding.
    const float* base = in + (size_t)b * D_DIM + d + (size_t)(g * 8) * FB_STRIDE;
    float acc = 0.f;
#pragma unroll
    for (int k = 0; k < 8; k++)
        acc += __ldg(base + (size_t)k * FB_STRIDE);
    partial[g][d] = acc;
    __syncthreads();

    if (g == 0) {
        s[d] = partial[0][d] + partial[1][d] + partial[2][d] + partial[3][d];
    }
    __syncthreads();

    // Outer product: 64x64 = 4096 floats = 1024 float4 stores, coalesced
    // (each warp writes 512B contiguous). ~70% of output lines sticky in L2
    // across replays -> write-hits on resident dirty lines.
    float4* o4 = reinterpret_cast<float4*>(out + (size_t)b * (D_DIM * D_DIM));
    const float4* s4 = reinterpret_cast<const float4*>(s);

#pragma unroll
    for (int r = 0; r < 4; r++) {
        const int idx = tid + r * 256;   // float4 index 0..1023
        const int i   = idx >> 4;        // output row (16 float4 per row)
        const int jc  = idx & 15;        // column chunk
        const float  si = s[i];
        const float4 v  = s4[jc];
        float4 w;
        w.x = si * v.x;
        w.y = si * v.y;
        w.z = si * v.z;
        w.w = si * v.w;
        stg_v4_hint(o4 + idx, w, pol);
    }
}

extern "C" void kernel_launch(void* const* d_in, const int* in_sizes, int n_in,
                              void* d_out, int out_size) {
    const float* in = (const float*)d_in[0];
    float* out = (float*)d_out;
    opnn_kernel<<<B_DIM, 256>>>(in, out);
}

// round 12
// speedup vs baseline: 1.0063x; 1.0063x over previous
#include <cuda_runtime.h>
#include <cstdint>

// F=32, B=8192, D=64
// inputs: [F, B, 1, D] fp32 ; output: [B, D*D] fp32
// out[b, i*64+j] = s[b,i] * s[b,j], s = sum_f inputs[f,b,0,:]
//
// R12: final structural probe — 2 samples per 512-thread CTA (grid 4096).
// Halves CTA launch count, barrier instances per byte, and improves wave-tail
// rounding. DRAM-bound model predicts neutral; this closes the last axis.

#define F_DIM 32
#define B_DIM 8192
#define D_DIM 64
#define FB_STRIDE ((size_t)B_DIM * D_DIM)   // elements per field slab
#define OUT_TILE (D_DIM * D_DIM)

__device__ __forceinline__ uint64_t make_policy_f70() {
    uint64_t pol;
    asm("createpolicy.fractional.L2::evict_last.b64 %0, 0.7;" : "=l"(pol));
    return pol;
}

__device__ __forceinline__ void stg_v4_hint(float4* p, float4 v, uint64_t pol) {
    asm volatile(
        "st.global.L2::cache_hint.v4.f32 [%0], {%1, %2, %3, %4}, %5;"
        :: "l"(p), "f"(v.x), "f"(v.y), "f"(v.z), "f"(v.w), "l"(pol)
        : "memory");
}

__global__ __launch_bounds__(512, 4)
void opnn_kernel(const float* __restrict__ in, float* __restrict__ out) {
    const int tid  = threadIdx.x;       // 0..511
    const int half = tid >> 8;          // 0 or 1: which sample
    const int t    = tid & 255;         // 0..255 within the half
    const int b    = blockIdx.x * 2 + half;

    const int d = t & 63;               // 0..63
    const int g = t >> 6;               // 0..3 (field group of 8)

    __shared__ float partial[2][4][64];
    __shared__ float s[2][64];

    const uint64_t pol = make_policy_f70();

    // Field-sum for this half's sample: each thread sums 8 fields for one d.
    // Per-field access is a contiguous 256B line across d (coalesced);
    // 8 independent loads -> MLP.
    const float* base = in + (size_t)b * D_DIM + d + (size_t)(g * 8) * FB_STRIDE;
    float acc = 0.f;
#pragma unroll
    for (int k = 0; k < 8; k++)
        acc += __ldg(base + (size_t)k * FB_STRIDE);
    partial[half][g][d] = acc;
    __syncthreads();

    if (g == 0) {
        s[half][d] = partial[half][0][d] + partial[half][1][d] +
                     partial[half][2][d] + partial[half][3][d];
    }
    __syncthreads();

    // Outer product per half: 64x64 = 1024 float4 stores, coalesced.
    float4* o4 = reinterpret_cast<float4*>(out + (size_t)b * OUT_TILE);
    const float4* s4 = reinterpret_cast<const float4*>(s[half]);

#pragma unroll
    for (int r = 0; r < 4; r++) {
        const int idx = t + r * 256;     // float4 index 0..1023
        const int i   = idx >> 4;        // output row (16 float4 per row)
        const int jc  = idx & 15;        // column chunk
        const float  si = s[half][i];
        const float4 v  = s4[jc];
        float4 w;
        w.x = si * v.x;
        w.y = si * v.y;
        w.z = si * v.z;
        w.w = si * v.w;
        stg_v4_hint(o4 + idx, w, pol);
    }
}

extern "C" void kernel_launch(void* const* d_in, const int* in_sizes, int n_in,
                              void* d_out, int out_size) {
    const float* in = (const float*)d_in[0];
    float* out = (float*)d_out;
    opnn_kernel<<<B_DIM / 2, 512>>>(in, out);
}

// round 13
// speedup vs baseline: 1.0165x; 1.0101x over previous
#include <cuda_runtime.h>

// F=32, B=8192, D=64
// inputs: [F, B, 1, D] fp32 ; output: [B, D*D] fp32
// out[b, i*64+j] = s[b,i] * s[b,j], s = sum_f inputs[f,b,0,:]
//
// FINAL — 12-round optimization sweep concluded this kernel is compulsory-
// traffic bound: 134MB output writes per replay (+64MB L2-resident input
// reads) at the chip's mixed-stream DRAM ceiling (~5.6TB/s wall-effective).
// Seven structurally distinct datapaths (STG widths 128/256b, .wt/.cs,
// L2 createpolicy residency pinning of input/output/fractional, TMA bulk
// async store, persistent pipelined grid, 1- and 2-sample CTAs) all measured
// 35.3-35.6us wall (noise band +-0.3us). This is the simplest variant in
// that optimal band.

#define F_DIM 32
#define B_DIM 8192
#define D_DIM 64
#define FB_STRIDE ((size_t)B_DIM * D_DIM)   // elements per field slab

__global__ __launch_bounds__(256, 8)
void opnn_kernel(const float* __restrict__ in, float* __restrict__ out) {
    const int b   = blockIdx.x;
    const int tid = threadIdx.x;      // 256 threads
    const int d   = tid & 63;         // 0..63
    const int g   = tid >> 6;         // 0..3 (field group of 8)

    __shared__ float partial[4][64];
    __shared__ float s[64];

    // Field-sum: each thread sums 8 fields for one d. Per-field access is a
    // contiguous 256B line across d (fully coalesced); 8 independent loads
    // give MLP for latency hiding.
    const float* base = in + (size_t)b * D_DIM + d + (size_t)(g * 8) * FB_STRIDE;
    float acc = 0.f;
#pragma unroll
    for (int k = 0; k < 8; k++)
        acc += __ldg(base + (size_t)k * FB_STRIDE);
    partial[g][d] = acc;
    __syncthreads();

    if (g == 0) {
        s[d] = partial[0][d] + partial[1][d] + partial[2][d] + partial[3][d];
    }
    __syncthreads();

    // Outer product: 64x64 = 4096 floats = 1024 float4 stores; each warp
    // writes 512B contiguous (full-sector coalescing).
    float4* o4 = reinterpret_cast<float4*>(out + (size_t)b * (D_DIM * D_DIM));
    const float4* s4 = reinterpret_cast<const float4*>(s);

#pragma unroll
    for (int r = 0; r < 4; r++) {
        const int idx = tid + r * 256;   // float4 index 0..1023
        const int i   = idx >> 4;        // output row (16 float4 per row)
        const int jc  = idx & 15;        // column chunk
        const float  si = s[i];
        const float4 v  = s4[jc];
        float4 w;
        w.x = si * v.x;
        w.y = si * v.y;
        w.z = si * v.z;
        w.w = si * v.w;
        o4[idx] = w;
    }
}

extern "C" void kernel_launch(void* const* d_in, const int* in_sizes, int n_in,
                              void* d_out, int out_size) {
    const float* in = (const float*)d_in[0];
    float* out = (float*)d_out;
    opnn_kernel<<<B_DIM, 256>>>(in, out);
}